// round 4
// baseline (speedup 1.0000x reference)
#include <cuda_runtime.h>
#include <cuda_bf16.h>
#include <cstdint>

// Problem constants (fixed by the dataset): input [B, C, T] fp32
#define B_DIM 16
#define C_DIM 256
#define T_DIM 16000
#define TILE_T 32                        // timesteps per tile (== warp width)
#define NT (T_DIM / TILE_T)              // 500 tiles per batch (exact)
#define NTOT (B_DIM * NT)                // 8000 tiles
#define NWARPS 8
#define CPW (C_DIM / NWARPS)             // 32 channels per warp
#define EPS 1e-8f

// ---- lookback scratch (device globals: no allocation allowed) ----
__device__ int   g_counter;
__device__ int   g_flag[NTOT];           // 0=invalid, 1=aggregate ready, 2=inclusive ready
__device__ float g_aggS[NTOT], g_aggP[NTOT];
__device__ float g_incS[NTOT], g_incP[NTOT];

__global__ void reset_kernel() {
    int i = blockIdx.x * blockDim.x + threadIdx.x;
    if (i == 0) g_counter = 0;
    if (i < NTOT) g_flag[i] = 0;
}

__global__ __launch_bounds__(256, 4) void cln_kernel(
    const float* __restrict__ x,
    const float* __restrict__ gain,
    const float* __restrict__ bias,
    float* __restrict__ out)
{
    __shared__ float spS[NWARPS][TILE_T];
    __shared__ float spP[NWARPS][TILE_T];
    __shared__ float s_cumS[TILE_T];
    __shared__ float s_cumP[TILE_T];
    __shared__ float s_gain[C_DIM];
    __shared__ float s_bias[C_DIM];
    __shared__ int   s_ticket;

    const int tid  = threadIdx.x;
    const int w    = tid >> 5;
    const int lane = tid & 31;

    // Dynamic ticket: claim order == atomicAdd order -> all predecessors of a
    // claimed tile are held by blocks already running -> lookback deadlock-free.
    if (tid == 0) s_ticket = atomicAdd(&g_counter, 1);
    s_gain[tid] = gain[tid];
    s_bias[tid] = bias[tid];
    __syncthreads();

    const int r    = s_ticket;
    const int b    = r / NT;
    const int tile = r % NT;
    const int t    = tile * TILE_T + lane;          // this thread's timestep

    const size_t base = (size_t)b * C_DIM * T_DIM + (size_t)(w * CPW) * T_DIM + t;
    const float* px = x + base;

    // ---------- Phase 1: load tile into registers, partial (sum, sumsq) ----------
    float v[CPW];
    float s = 0.f, p = 0.f;
    #pragma unroll
    for (int cc = 0; cc < CPW; cc++) {
        v[cc] = px[(size_t)cc * T_DIM];             // coalesced 128B per warp
    }
    #pragma unroll
    for (int cc = 0; cc < CPW; cc++) {
        s += v[cc];
        p = fmaf(v[cc], v[cc], p);
    }
    spS[w][lane] = s;
    spP[w][lane] = p;
    __syncthreads();

    // ---------- Warp 0: combine warps, shuffle scan, warp-parallel lookback ----------
    if (w == 0) {
        float ts = 0.f, tp = 0.f;
        #pragma unroll
        for (int ww = 0; ww < NWARPS; ww++) { ts += spS[ww][lane]; tp += spP[ww][lane]; }

        // inclusive scan over the 32 timesteps
        #pragma unroll
        for (int off = 1; off < 32; off <<= 1) {
            float ns = __shfl_up_sync(0xffffffffu, ts, off);
            float np = __shfl_up_sync(0xffffffffu, tp, off);
            if (lane >= off) { ts += ns; tp += np; }
        }
        const float aggS = __shfl_sync(0xffffffffu, ts, 31);
        const float aggP = __shfl_sync(0xffffffffu, tp, 31);

        const int idx = r;
        const int chain_start = b * NT;
        volatile int*   vflag = g_flag;
        volatile float* vaS = g_aggS; volatile float* vaP = g_aggP;
        volatile float* viS = g_incS; volatile float* viP = g_incP;

        float excS = 0.f, excP = 0.f;

        if (tile == 0) {
            // Chain start publishes ONLY inclusive (flag=2): walkers can't pass it.
            if (lane == 0) {
                viS[idx] = aggS; viP[idx] = aggP;
                __threadfence();
                vflag[idx] = 2;
            }
        } else {
            if (lane == 0) {
                vaS[idx] = aggS; vaP[idx] = aggP;
                __threadfence();
                vflag[idx] = 1;
            }
            // Warp-parallel windowed lookback: 32 predecessors per probe.
            int windowEnd = idx - 1;
            while (true) {
                const int  pred = windowEnd - lane;
                const bool inr  = (pred >= chain_start);
                int f;
                do { f = inr ? vflag[pred] : 2; }
                while (__ballot_sync(0xffffffffu, f == 0));
                __threadfence();

                const unsigned m2 = __ballot_sync(0xffffffffu, inr && (f == 2));
                const int stop = __ffs(m2) - 1;     // lowest lane with inclusive; -1 if none
                float aS = 0.f, aP = 0.f;
                if (inr && (stop < 0 || lane <= stop)) {
                    if (lane == stop) { aS = viS[pred]; aP = viP[pred]; }
                    else              { aS = vaS[pred]; aP = vaP[pred]; }
                }
                #pragma unroll
                for (int off = 16; off; off >>= 1) {
                    aS += __shfl_xor_sync(0xffffffffu, aS, off);
                    aP += __shfl_xor_sync(0xffffffffu, aP, off);
                }
                excS += aS; excP += aP;              // identical on all lanes
                if (stop >= 0) break;
                windowEnd -= 32;
            }
            if (lane == 0) {
                viS[idx] = excS + aggS; viP[idx] = excP + aggP;
                __threadfence();
                vflag[idx] = 2;
            }
        }
        s_cumS[lane] = excS + ts;
        s_cumP[lane] = excP + tp;
    }
    __syncthreads();

    // ---------- Phase 2: normalize from registers, write ----------
    const float cumS = s_cumS[lane];
    const float cumP = s_cumP[lane];
    const float cnt  = (float)(t + 1) * (float)C_DIM;
    const float mean = cumS / cnt;
    const float inv  = rsqrtf(cumP / cnt - mean * mean + EPS);

    float* po = out + base;
    #pragma unroll
    for (int cc = 0; cc < CPW; cc++) {
        const int c = w * CPW + cc;
        po[(size_t)cc * T_DIM] = fmaf((v[cc] - mean) * inv, s_gain[c], s_bias[c]);
    }
}

extern "C" void kernel_launch(void* const* d_in, const int* in_sizes, int n_in,
                              void* d_out, int out_size)
{
    const float* x    = (const float*)d_in[0];
    const float* gain = (const float*)d_in[1];
    const float* bias = (const float*)d_in[2];
    float* out = (float*)d_out;

    reset_kernel<<<(NTOT + 255) / 256, 256>>>();
    cln_kernel<<<NTOT, 256>>>(x, gain, bias, out);
}